// round 3
// baseline (speedup 1.0000x reference)
#include <cuda_runtime.h>
#include <cuda_bf16.h>

#define HH 2048
#define WW 2048

// One CTA = one 32x32 pixel tile of one batch image.
// Fuses: dequant + separable 8x8 IDCT (Y + Cb + Cr) + 2x chroma upsample +
// color conversion + clip, writing RGB directly. No intermediate gmem planes.
__global__ __launch_bounds__(256) void jpeg_decode_kernel(
    const float* __restrict__ ycoef, const float* __restrict__ cbcoef,
    const float* __restrict__ crcoef,
    const float* __restrict__ y_table, const float* __restrict__ c_table,
    const float* __restrict__ alpha, const float* __restrict__ shift,
    const float* __restrict__ matrix, const int* __restrict__ factor_i,
    float* __restrict__ out)
{
    __shared__ float sC[64];      // cosine matrix C[f][p] = cos((2p+1)f*pi/16)
    __shared__ float sD[128];     // dequant: [0:64) Y, [64:128) chroma (x 0.25*factor)
    __shared__ float sMat[9];
    __shared__ float sShift[3];
    __shared__ float sCoef[1536]; // 24 blocks x 64 ; reused as pixel buffer after pass2
    __shared__ float sTmp[1536];

    const int tid = threadIdx.x;
    const int tx = blockIdx.x, ty = blockIdx.y, bz = blockIdx.z;
    const int Wb8 = WW / 8, Wb16 = WW / 16;
    const long nY = (long)(HH / 8) * (WW / 8);
    const long nC = (long)(HH / 16) * (WW / 16);

    // factor may arrive as int32 or float32 bits; 1 in this dataset.
    int fbits = factor_i[0];
    float fac = (fbits > 0 && fbits < (1 << 23)) ? (float)fbits
                                                 : __int_as_float(fbits);

    if (tid < 64) {
        int f = tid >> 3, p = tid & 7;
        sC[tid] = cospif((float)((2 * p + 1) * f) / 16.0f);
    } else if (tid < 128) {
        int o = tid - 64;
        sD[o] = y_table[o] * alpha[o] * fac * 0.25f;
    } else if (tid < 192) {
        int o = tid - 128;
        sD[64 + o] = c_table[o] * alpha[o] * fac * 0.25f;
    } else if (tid < 201) {
        sMat[tid - 192] = matrix[tid - 192];
    } else if (tid < 204) {
        sShift[tid - 201] = shift[tid - 201];
    }

    // ---- load 24 coefficient blocks (1536 floats) into registers, coalesced ----
    float rc[6];
#pragma unroll
    for (int k = 0; k < 6; k++) {
        int e = tid + k * 256;
        int q = e >> 6, o = e & 63;
        const float* src;
        long n;
        if (q < 16) {                       // Y blocks: 4x4 arrangement
            int i = q >> 2, j = q & 3;
            n = (long)bz * nY + (long)(ty * 4 + i) * Wb8 + (tx * 4 + j);
            src = ycoef;
        } else if (q < 20) {                // Cb blocks: 2x2
            int i = (q - 16) >> 1, j = q & 1;
            n = (long)bz * nC + (long)(ty * 2 + i) * Wb16 + (tx * 2 + j);
            src = cbcoef;
        } else {                            // Cr blocks: 2x2
            int i = (q - 20) >> 1, j = q & 1;
            n = (long)bz * nC + (long)(ty * 2 + i) * Wb16 + (tx * 2 + j);
            src = crcoef;
        }
        rc[k] = src[n * 64 + o];
    }
    __syncthreads();

    // Per-thread invariant column indices: e%8 and (e%64)/8 are constant over k.
    const int v = tid & 7;
    const int u = (tid & 63) >> 3;
    float Cv[8], Cu[8];
#pragma unroll
    for (int i = 0; i < 8; i++) {
        Cv[i] = sC[i * 8 + v];
        Cu[i] = sC[i * 8 + u];
    }

    // dequant + store to smem
#pragma unroll
    for (int k = 0; k < 6; k++) {
        int e = tid + k * 256;
        int q = e >> 6, o = e & 63;
        sCoef[e] = rc[k] * sD[(q < 16 ? 0 : 64) + o];
    }
    __syncthreads();

    // ---- IDCT pass 1 (over y): tmp[q][x][v] = sum_y coef[q][x][y] * C[y][v] ----
#pragma unroll
    for (int k = 0; k < 6; k++) {
        int e = tid + k * 256;
        int base = e & ~7;  // q*64 + x*8
        float acc = 0.0f;
#pragma unroll
        for (int yy = 0; yy < 8; yy++)
            acc = fmaf(sCoef[base + yy], Cv[yy], acc);
        sTmp[e] = acc;
    }
    __syncthreads();

    // ---- IDCT pass 2 (over x): pix[q][u][v] = sum_x tmp[q][x][v]*C[x][u] + 128 ----
#pragma unroll
    for (int k = 0; k < 6; k++) {
        int e = tid + k * 256;
        int q6 = e & ~63;  // q*64
        float acc = 0.0f;
#pragma unroll
        for (int xx = 0; xx < 8; xx++)
            acc = fmaf(sTmp[q6 + xx * 8 + v], Cu[xx], acc);
        sCoef[e] = acc + 128.0f;  // reuse sCoef as pixel buffer
    }
    __syncthreads();

    // ---- chroma upsample + color convert + clip; float4 stores per channel ----
    const int p0 = tid * 4;
    const int py = p0 >> 5;
    const int px0 = p0 & 31;

    float oR[4], oG[4], oB[4];
#pragma unroll
    for (int i = 0; i < 4; i++) {
        int px = px0 + i;
        int yq = ((py >> 3) << 2) + (px >> 3);
        float Yv = sCoef[yq * 64 + ((py & 7) << 3) + (px & 7)] + sShift[0];
        int cy = py >> 1, cx = px >> 1;
        int co = ((cy & 7) << 3) + (cx & 7);
        int cq = 16 + ((cy >> 3) << 1) + (cx >> 3);
        float Cbv = sCoef[cq * 64 + co] + sShift[1];
        float Crv = sCoef[(cq + 4) * 64 + co] + sShift[2];
        // rgb[d] = sum_c ycc[c] * matrix[c][d]
        float r = fmaf(Yv, sMat[0], fmaf(Cbv, sMat[3], Crv * sMat[6]));
        float g = fmaf(Yv, sMat[1], fmaf(Cbv, sMat[4], Crv * sMat[7]));
        float b = fmaf(Yv, sMat[2], fmaf(Cbv, sMat[5], Crv * sMat[8]));
        oR[i] = fminf(fmaxf(r, 0.0f), 255.0f) * (1.0f / 255.0f);
        oG[i] = fminf(fmaxf(g, 0.0f), 255.0f) * (1.0f / 255.0f);
        oB[i] = fminf(fmaxf(b, 0.0f), 255.0f) * (1.0f / 255.0f);
    }

    const long gy = (long)ty * 32 + py;
    const long gx = (long)tx * 32 + px0;
    float* outR = out + (((long)bz * 3 + 0) * HH + gy) * WW + gx;
    float* outG = out + (((long)bz * 3 + 1) * HH + gy) * WW + gx;
    float* outB = out + (((long)bz * 3 + 2) * HH + gy) * WW + gx;
    *reinterpret_cast<float4*>(outR) = make_float4(oR[0], oR[1], oR[2], oR[3]);
    *reinterpret_cast<float4*>(outG) = make_float4(oG[0], oG[1], oG[2], oG[3]);
    *reinterpret_cast<float4*>(outB) = make_float4(oB[0], oB[1], oB[2], oB[3]);
}

extern "C" void kernel_launch(void* const* d_in, const int* in_sizes, int n_in,
                              void* d_out, int out_size) {
    const float* y      = (const float*)d_in[0];
    const float* cb     = (const float*)d_in[1];
    const float* cr     = (const float*)d_in[2];
    const float* ytab   = (const float*)d_in[3];
    const float* ctab   = (const float*)d_in[4];
    const float* alpha  = (const float*)d_in[5];
    // d_in[6] = dct_tensor (unused; cosine basis regenerated via cospif)
    const float* shift  = (const float*)d_in[7];
    const float* matrix = (const float*)d_in[8];
    // d_in[9] = image_height, d_in[10] = image_width (fixed 2048 for this problem)
    const int* factor   = (const int*)d_in[11];

    int B = in_sizes[0] / (2048 * 2048);  // y elems = B*H*W
    if (B < 1) B = 1;

    dim3 grid(WW / 32, HH / 32, B);
    jpeg_decode_kernel<<<grid, 256>>>(y, cb, cr, ytab, ctab, alpha, shift,
                                      matrix, factor, (float*)d_out);
}

// round 4
// speedup vs baseline: 1.3905x; 1.3905x over previous
#include <cuda_runtime.h>
#include <cuda_bf16.h>

#define HH 2048
#define WW 2048

// Cosine matrix C[f][p] = cos((2p+1)*f*pi/16), hard-coded so the fully
// unrolled IDCT passes compile to FFMA-with-immediate (no LDS in the passes).
__device__ constexpr float CM[8][8] = {
  { 1.0f,         1.0f,         1.0f,         1.0f,         1.0f,         1.0f,         1.0f,         1.0f        },
  { 0.98078528f,  0.83146961f,  0.55557023f,  0.19509032f, -0.19509032f, -0.55557023f, -0.83146961f, -0.98078528f },
  { 0.92387953f,  0.38268343f, -0.38268343f, -0.92387953f, -0.92387953f, -0.38268343f,  0.38268343f,  0.92387953f },
  { 0.83146961f, -0.19509032f, -0.98078528f, -0.55557023f,  0.55557023f,  0.98078528f,  0.19509032f, -0.83146961f },
  { 0.70710678f, -0.70710678f, -0.70710678f,  0.70710678f,  0.70710678f, -0.70710678f, -0.70710678f,  0.70710678f },
  { 0.55557023f, -0.98078528f,  0.19509032f,  0.83146961f, -0.83146961f, -0.19509032f,  0.98078528f, -0.55557023f },
  { 0.38268343f, -0.92387953f,  0.92387953f, -0.38268343f, -0.38268343f,  0.92387953f, -0.92387953f,  0.38268343f },
  { 0.19509032f, -0.55557023f,  0.83146961f, -0.98078528f,  0.98078528f, -0.83146961f,  0.55557023f, -0.19509032f },
};

// One CTA = one 32x32 pixel tile. 24 blocks (16Y + 4Cb + 4Cr) = 192 rows;
// threads 0..191 each own one 8-float row. IDCT passes are register-resident;
// only the transpose and the pixel buffer touch shared memory, both with a
// 9-stride padded layout (q*72 + r*9 + c) that is bank-conflict-free for all
// access patterns used here.
__global__ __launch_bounds__(256) void jpeg_decode_kernel(
    const float* __restrict__ ycoef, const float* __restrict__ cbcoef,
    const float* __restrict__ crcoef,
    const float* __restrict__ y_table, const float* __restrict__ c_table,
    const float* __restrict__ alpha, const float* __restrict__ shift,
    const float* __restrict__ matrix, const int* __restrict__ factor_i,
    float* __restrict__ out)
{
    __shared__ float sD[128];     // dequant scale: [0:64) Y, [64:128) chroma
    __shared__ float sMat[9];
    __shared__ float sShift[3];
    __shared__ float sT[1728];    // transpose buffer, 24 * 72
    __shared__ float sP[1728];    // pixel buffer,     24 * 72

    const int tid = threadIdx.x;
    const int tx = blockIdx.x, ty = blockIdx.y, bz = blockIdx.z;
    const int Wb8 = WW / 8, Wb16 = WW / 16;
    const long nY = (long)(HH / 8) * (WW / 8);
    const long nC = (long)(HH / 16) * (WW / 16);

    int fbits = factor_i[0];
    float fac = (fbits > 0 && fbits < (1 << 23)) ? (float)fbits
                                                 : __int_as_float(fbits);

    if (tid < 128) {
        const float* tab = (tid < 64) ? y_table : c_table;
        int o = tid & 63;
        sD[tid] = tab[o] * alpha[o] * fac * 0.25f;
    } else if (tid < 137) {
        sMat[tid - 128] = matrix[tid - 128];
    } else if (tid < 140) {
        sShift[tid - 137] = shift[tid - 137];
    }

    const int q = tid >> 3;
    const int x = tid & 7;

    float4 ra, rb;
    if (tid < 192) {
        const float* src;
        long n;
        if (q < 16) {                       // Y blocks: 4x4 arrangement
            int i = q >> 2, j = q & 3;
            n = (long)bz * nY + (long)(ty * 4 + i) * Wb8 + (tx * 4 + j);
            src = ycoef;
        } else if (q < 20) {                // Cb blocks: 2x2
            int i = (q - 16) >> 1, j = q & 1;
            n = (long)bz * nC + (long)(ty * 2 + i) * Wb16 + (tx * 2 + j);
            src = cbcoef;
        } else {                            // Cr blocks: 2x2
            int i = (q - 20) >> 1, j = q & 1;
            n = (long)bz * nC + (long)(ty * 2 + i) * Wb16 + (tx * 2 + j);
            src = crcoef;
        }
        const float4* g = (const float4*)(src + n * 64 + x * 8);
        ra = g[0];
        rb = g[1];
    }
    __syncthreads();

    if (tid < 192) {
        // dequant (scale row from smem, broadcast-friendly)
        const int db = (q < 16 ? 0 : 64) + x * 8;
        float4 da = *(const float4*)&sD[db];
        float4 db4 = *(const float4*)&sD[db + 4];
        float a0 = ra.x * da.x, a1 = ra.y * da.y, a2 = ra.z * da.z, a3 = ra.w * da.w;
        float a4 = rb.x * db4.x, a5 = rb.y * db4.y, a6 = rb.z * db4.z, a7 = rb.w * db4.w;

        // pass 1 (over y), all-immediate FMAs: t[v] = sum_y a[y]*CM[y][v]
        float* d = &sT[q * 72 + x * 9];
#pragma unroll
        for (int v = 0; v < 8; v++) {
            float acc = a0 * CM[0][v];
            acc = fmaf(a1, CM[1][v], acc);
            acc = fmaf(a2, CM[2][v], acc);
            acc = fmaf(a3, CM[3][v], acc);
            acc = fmaf(a4, CM[4][v], acc);
            acc = fmaf(a5, CM[5][v], acc);
            acc = fmaf(a6, CM[6][v], acc);
            acc = fmaf(a7, CM[7][v], acc);
            d[v] = acc;
        }
    }
    __syncthreads();

    if (tid < 192) {
        const int v = x;  // this thread now owns column v of block q
        float c0 = sT[q * 72 + 0 * 9 + v];
        float c1 = sT[q * 72 + 1 * 9 + v];
        float c2 = sT[q * 72 + 2 * 9 + v];
        float c3 = sT[q * 72 + 3 * 9 + v];
        float c4 = sT[q * 72 + 4 * 9 + v];
        float c5 = sT[q * 72 + 5 * 9 + v];
        float c6 = sT[q * 72 + 6 * 9 + v];
        float c7 = sT[q * 72 + 7 * 9 + v];

        // pass 2 (over x): p[u] = sum_x c[x]*CM[x][u] ; +128 level shift
#pragma unroll
        for (int u = 0; u < 8; u++) {
            float acc = c0 * CM[0][u];
            acc = fmaf(c1, CM[1][u], acc);
            acc = fmaf(c2, CM[2][u], acc);
            acc = fmaf(c3, CM[3][u], acc);
            acc = fmaf(c4, CM[4][u], acc);
            acc = fmaf(c5, CM[5][u], acc);
            acc = fmaf(c6, CM[6][u], acc);
            acc = fmaf(c7, CM[7][u], acc);
            sP[q * 72 + u * 9 + v] = acc + 128.0f;
        }
    }
    __syncthreads();

    // ---- chroma upsample + color convert + clip; float4 stores per channel ----
    const int p0 = tid * 4;
    const int py = p0 >> 5;          // 0..31
    const int px0 = p0 & 31;         // 0,4,...,28

    float oR[4], oG[4], oB[4];
#pragma unroll
    for (int i = 0; i < 4; i++) {
        int px = px0 + i;
        int yq = ((py >> 3) << 2) + (px >> 3);
        float Yv = sP[yq * 72 + (py & 7) * 9 + (px & 7)] + sShift[0];
        int cy = py >> 1, cx = px >> 1;
        int co = (cy & 7) * 9 + (cx & 7);
        int cq = 16 + ((cy >> 3) << 1) + (cx >> 3);
        float Cbv = sP[cq * 72 + co] + sShift[1];
        float Crv = sP[(cq + 4) * 72 + co] + sShift[2];
        float r = fmaf(Yv, sMat[0], fmaf(Cbv, sMat[3], Crv * sMat[6]));
        float g = fmaf(Yv, sMat[1], fmaf(Cbv, sMat[4], Crv * sMat[7]));
        float b = fmaf(Yv, sMat[2], fmaf(Cbv, sMat[5], Crv * sMat[8]));
        oR[i] = fminf(fmaxf(r, 0.0f), 255.0f) * (1.0f / 255.0f);
        oG[i] = fminf(fmaxf(g, 0.0f), 255.0f) * (1.0f / 255.0f);
        oB[i] = fminf(fmaxf(b, 0.0f), 255.0f) * (1.0f / 255.0f);
    }

    const long gy = (long)ty * 32 + py;
    const long gx = (long)tx * 32 + px0;
    float* outR = out + (((long)bz * 3 + 0) * HH + gy) * WW + gx;
    float* outG = out + (((long)bz * 3 + 1) * HH + gy) * WW + gx;
    float* outB = out + (((long)bz * 3 + 2) * HH + gy) * WW + gx;
    *reinterpret_cast<float4*>(outR) = make_float4(oR[0], oR[1], oR[2], oR[3]);
    *reinterpret_cast<float4*>(outG) = make_float4(oG[0], oG[1], oG[2], oG[3]);
    *reinterpret_cast<float4*>(outB) = make_float4(oB[0], oB[1], oB[2], oB[3]);
}

extern "C" void kernel_launch(void* const* d_in, const int* in_sizes, int n_in,
                              void* d_out, int out_size) {
    const float* y      = (const float*)d_in[0];
    const float* cb     = (const float*)d_in[1];
    const float* cr     = (const float*)d_in[2];
    const float* ytab   = (const float*)d_in[3];
    const float* ctab   = (const float*)d_in[4];
    const float* alpha  = (const float*)d_in[5];
    // d_in[6] = dct_tensor (unused; cosine basis hard-coded)
    const float* shift  = (const float*)d_in[7];
    const float* matrix = (const float*)d_in[8];
    const int* factor   = (const int*)d_in[11];

    int B = in_sizes[0] / (2048 * 2048);
    if (B < 1) B = 1;

    dim3 grid(WW / 32, HH / 32, B);
    jpeg_decode_kernel<<<grid, 256>>>(y, cb, cr, ytab, ctab, alpha, shift,
                                      matrix, factor, (float*)d_out);
}

// round 5
// speedup vs baseline: 1.5843x; 1.1394x over previous
#include <cuda_runtime.h>
#include <cuda_bf16.h>

#define HH 2048
#define WW 2048

// Cosine matrix C[f][p] = cos((2p+1)*f*pi/16), hard-coded so the fully
// unrolled IDCT passes compile to FFMA-with-immediate (no LDS in the passes).
__device__ constexpr float CM[8][8] = {
  { 1.0f,         1.0f,         1.0f,         1.0f,         1.0f,         1.0f,         1.0f,         1.0f        },
  { 0.98078528f,  0.83146961f,  0.55557023f,  0.19509032f, -0.19509032f, -0.55557023f, -0.83146961f, -0.98078528f },
  { 0.92387953f,  0.38268343f, -0.38268343f, -0.92387953f, -0.92387953f, -0.38268343f,  0.38268343f,  0.92387953f },
  { 0.83146961f, -0.19509032f, -0.98078528f, -0.55557023f,  0.55557023f,  0.98078528f,  0.19509032f, -0.83146961f },
  { 0.70710678f, -0.70710678f, -0.70710678f,  0.70710678f,  0.70710678f, -0.70710678f, -0.70710678f,  0.70710678f },
  { 0.55557023f, -0.98078528f,  0.19509032f,  0.83146961f, -0.83146961f, -0.19509032f,  0.98078528f, -0.55557023f },
  { 0.38268343f, -0.92387953f,  0.92387953f, -0.38268343f, -0.38268343f,  0.92387953f, -0.92387953f,  0.38268343f },
  { 0.19509032f, -0.55557023f,  0.83146961f, -0.98078528f,  0.98078528f, -0.83146961f,  0.55557023f, -0.19509032f },
};

// One CTA = one 32x32 RGB tile. 24 blocks (16Y+4Cb+4Cr); threads 0..191 own
// one 8-float row each for the register-resident IDCT. Pass-2 writes straight
// into PLANAR padded pixel buffers (Y 32x33, chroma 16x17), so the epilogue is
// pure streaming: no block-index math, folded affine color transform.
__global__ __launch_bounds__(256) void jpeg_decode_kernel(
    const float* __restrict__ ycoef, const float* __restrict__ cbcoef,
    const float* __restrict__ crcoef,
    const float* __restrict__ y_table, const float* __restrict__ c_table,
    const float* __restrict__ alpha, const float* __restrict__ shift,
    const float* __restrict__ matrix, const int* __restrict__ factor_i,
    float* __restrict__ out)
{
    __shared__ float sD[128];       // dequant scale: [0:64) Y, [64:128) chroma
    __shared__ float sM[9];         // matrix / 255  (sM[c*3+d])
    __shared__ float sK[3];         // folded constants per output channel
    __shared__ float sT[1728];      // transpose buffer, 24 * 72
    __shared__ float sPY[32 * 33];  // planar Y pixels (raw idct, no +128)
    __shared__ float sPCb[16 * 17];
    __shared__ float sPCr[16 * 17];

    const int tid = threadIdx.x;
    const int tx = blockIdx.x, ty = blockIdx.y, bz = blockIdx.z;
    const int Wb8 = WW / 8, Wb16 = WW / 16;
    const long nY = (long)(HH / 8) * (WW / 8);
    const long nC = (long)(HH / 16) * (WW / 16);

    int fbits = factor_i[0];
    float fac = (fbits > 0 && fbits < (1 << 23)) ? (float)fbits
                                                 : __int_as_float(fbits);

    if (tid < 128) {
        const float* tab = (tid < 64) ? y_table : c_table;
        int o = tid & 63;
        sD[tid] = tab[o] * alpha[o] * fac * 0.25f;
    } else if (tid < 137) {
        sM[tid - 128] = matrix[tid - 128] * (1.0f / 255.0f);
    } else if (tid < 140) {
        // const_d = sum_c (128 + shift[c]) * matrix[c*3+d] / 255
        int d = tid - 137;
        float k = 0.0f;
#pragma unroll
        for (int c = 0; c < 3; c++)
            k = fmaf(128.0f + shift[c], matrix[c * 3 + d], k);
        sK[d] = k * (1.0f / 255.0f);
    }

    const int q = tid >> 3;
    const int x = tid & 7;

    float4 ra, rb;
    if (tid < 192) {
        const float* src;
        long n;
        if (q < 16) {                       // Y blocks: 4x4 arrangement
            int i = q >> 2, j = q & 3;
            n = (long)bz * nY + (long)(ty * 4 + i) * Wb8 + (tx * 4 + j);
            src = ycoef;
        } else if (q < 20) {                // Cb blocks: 2x2
            int i = (q - 16) >> 1, j = q & 1;
            n = (long)bz * nC + (long)(ty * 2 + i) * Wb16 + (tx * 2 + j);
            src = cbcoef;
        } else {                            // Cr blocks: 2x2
            int i = (q - 20) >> 1, j = q & 1;
            n = (long)bz * nC + (long)(ty * 2 + i) * Wb16 + (tx * 2 + j);
            src = crcoef;
        }
        const float4* g = (const float4*)(src + n * 64 + x * 8);
        ra = g[0];
        rb = g[1];
    }
    __syncthreads();

    if (tid < 192) {
        // dequant
        const int db = (q < 16 ? 0 : 64) + x * 8;
        float4 da = *(const float4*)&sD[db];
        float4 db4 = *(const float4*)&sD[db + 4];
        float a0 = ra.x * da.x, a1 = ra.y * da.y, a2 = ra.z * da.z, a3 = ra.w * da.w;
        float a4 = rb.x * db4.x, a5 = rb.y * db4.y, a6 = rb.z * db4.z, a7 = rb.w * db4.w;

        // pass 1 (over y), all-immediate FMAs
        float* d = &sT[q * 72 + x * 9];
#pragma unroll
        for (int v = 0; v < 8; v++) {
            float acc = a0 * CM[0][v];
            acc = fmaf(a1, CM[1][v], acc);
            acc = fmaf(a2, CM[2][v], acc);
            acc = fmaf(a3, CM[3][v], acc);
            acc = fmaf(a4, CM[4][v], acc);
            acc = fmaf(a5, CM[5][v], acc);
            acc = fmaf(a6, CM[6][v], acc);
            acc = fmaf(a7, CM[7][v], acc);
            d[v] = acc;
        }
    }
    __syncthreads();

    if (tid < 192) {
        const int v = x;  // this thread owns column v of block q
        float c0 = sT[q * 72 + 0 * 9 + v];
        float c1 = sT[q * 72 + 1 * 9 + v];
        float c2 = sT[q * 72 + 2 * 9 + v];
        float c3 = sT[q * 72 + 3 * 9 + v];
        float c4 = sT[q * 72 + 4 * 9 + v];
        float c5 = sT[q * 72 + 5 * 9 + v];
        float c6 = sT[q * 72 + 6 * 9 + v];
        float c7 = sT[q * 72 + 7 * 9 + v];

        // destination: planar buffer + stride, by block type
        float* dst;
        int stride;
        if (q < 16) {
            dst = &sPY[((q >> 2) * 8) * 33 + (q & 3) * 8 + v];
            stride = 33;
        } else if (q < 20) {
            int b = q - 16;
            dst = &sPCb[((b >> 1) * 8) * 17 + (b & 1) * 8 + v];
            stride = 17;
        } else {
            int b = q - 20;
            dst = &sPCr[((b >> 1) * 8) * 17 + (b & 1) * 8 + v];
            stride = 17;
        }

        // pass 2 (over x): raw idct values (level shift folded into epilogue)
#pragma unroll
        for (int u = 0; u < 8; u++) {
            float acc = c0 * CM[0][u];
            acc = fmaf(c1, CM[1][u], acc);
            acc = fmaf(c2, CM[2][u], acc);
            acc = fmaf(c3, CM[3][u], acc);
            acc = fmaf(c4, CM[4][u], acc);
            acc = fmaf(c5, CM[5][u], acc);
            acc = fmaf(c6, CM[6][u], acc);
            acc = fmaf(c7, CM[7][u], acc);
            dst[u * stride] = acc;
        }
    }
    __syncthreads();

    // ---- epilogue: 4 px per thread, folded color transform, saturate ----
    const int py = tid >> 3;           // 0..31
    const int px0 = (tid & 7) * 4;     // 0,4,...,28

    const float M0 = sM[0], M1 = sM[1], M2 = sM[2];
    const float M3 = sM[3], M4 = sM[4], M5 = sM[5];
    const float M6 = sM[6], M7 = sM[7], M8 = sM[8];
    const float K0 = sK[0], K1 = sK[1], K2 = sK[2];

    const int cy = py >> 1, cxb = px0 >> 1;
    const float* cbRow = &sPCb[cy * 17 + cxb];
    const float* crRow = &sPCr[cy * 17 + cxb];
    const float* yRow = &sPY[py * 33 + px0];

    // per 2x2-pair chroma bases (j = 0,1)
    float bR[2], bG[2], bB[2];
#pragma unroll
    for (int j = 0; j < 2; j++) {
        float cb = cbRow[j], cr = crRow[j];
        bR[j] = fmaf(cb, M3, fmaf(cr, M6, K0));
        bG[j] = fmaf(cb, M4, fmaf(cr, M7, K1));
        bB[j] = fmaf(cb, M5, fmaf(cr, M8, K2));
    }

    float oR[4], oG[4], oB[4];
#pragma unroll
    for (int i = 0; i < 4; i++) {
        float Yv = yRow[i];
        int j = i >> 1;
        oR[i] = __saturatef(fmaf(Yv, M0, bR[j]));
        oG[i] = __saturatef(fmaf(Yv, M1, bG[j]));
        oB[i] = __saturatef(fmaf(Yv, M2, bB[j]));
    }

    const long gy = (long)ty * 32 + py;
    const long gx = (long)tx * 32 + px0;
    float* outR = out + (((long)bz * 3 + 0) * HH + gy) * WW + gx;
    float* outG = out + (((long)bz * 3 + 1) * HH + gy) * WW + gx;
    float* outB = out + (((long)bz * 3 + 2) * HH + gy) * WW + gx;
    *reinterpret_cast<float4*>(outR) = make_float4(oR[0], oR[1], oR[2], oR[3]);
    *reinterpret_cast<float4*>(outG) = make_float4(oG[0], oG[1], oG[2], oG[3]);
    *reinterpret_cast<float4*>(outB) = make_float4(oB[0], oB[1], oB[2], oB[3]);
}

extern "C" void kernel_launch(void* const* d_in, const int* in_sizes, int n_in,
                              void* d_out, int out_size) {
    const float* y      = (const float*)d_in[0];
    const float* cb     = (const float*)d_in[1];
    const float* cr     = (const float*)d_in[2];
    const float* ytab   = (const float*)d_in[3];
    const float* ctab   = (const float*)d_in[4];
    const float* alpha  = (const float*)d_in[5];
    // d_in[6] = dct_tensor (unused; cosine basis hard-coded)
    const float* shift  = (const float*)d_in[7];
    const float* matrix = (const float*)d_in[8];
    const int* factor   = (const int*)d_in[11];

    int B = in_sizes[0] / (2048 * 2048);
    if (B < 1) B = 1;

    dim3 grid(WW / 32, HH / 32, B);
    jpeg_decode_kernel<<<grid, 256>>>(y, cb, cr, ytab, ctab, alpha, shift,
                                      matrix, factor, (float*)d_out);
}